// round 17
// baseline (speedup 1.0000x reference)
#include <cuda_runtime.h>
#include <cstdint>

// Problem constants
#define BS   32
#define CLS  80
#define HH   128
#define WW   128
#define HW   16384
#define K    100
#define CAND_CAP  3072
#define ABOVE_CAP 1024   // above-threshold cells (~152 expected, 65 sigma head)
#define FINAL_CAP 256

// Output layout (fp32, concatenated in reference return order)
#define OFF_SC   0                      // (32,80,100) per-class topk scores
#define OFF_IND  (BS*CLS*K)             // 256000
#define OFF_CLSO (OFF_IND + BS*K)       // 259200
#define OFF_YS   (OFF_CLSO + BS*K)      // 262400
#define OFF_XS   (OFF_YS + BS*K)        // 265600

// Scratch: per-class top-100 flat spatial indices
__device__ int g_idx1[BS * CLS * K];
// Per-batch completion counters (zero-init; reset by consumer -> graph-safe)
__device__ int g_done[BS];

// Inclusive suffix-scan over 256 histogram bins.
__device__ __forceinline__ void suffix_scan_store(const int* s_hist, int* s_scan,
                                                  int* s_red, int tid, int lane, int warp) {
    int incl = s_hist[255 - tid];
    #pragma unroll
    for (int o = 1; o < 32; o <<= 1) {
        int x = __shfl_up_sync(0xFFFFFFFFu, incl, o);
        if (lane >= o) incl += x;
    }
    if (lane == 31) s_red[warp] = incl;
    __syncthreads();
    int off = 0;
    #pragma unroll
    for (int w = 0; w < 8; ++w) off += (w < warp) ? s_red[w] : 0;
    s_scan[tid] = incl + off;
    __syncthreads();
}

// ---------------------------------------------------------------------------
// Fused kernel: one CTA per (b,c). Threshold-gated sparse NMS (dense scan for
// cells > T0, exact 8-neighbor verify on the sparse survivors, dense-NMS
// fallback if the filtered set can't cover top-100), SoA radix top-100,
// rank-emit; last CTA of each batch runs the global top-100 inline.
// ---------------------------------------------------------------------------
__global__ void __launch_bounds__(256, 6)
decode_kernel(const float* __restrict__ hm, float* __restrict__ out)
{
    __shared__ unsigned s_pool[2 * CAND_CAP];         // scores | indices (24 KB)
    __shared__ unsigned s_above[ABOVE_CAP];           // above-threshold cells (4 KB)
    __shared__ unsigned long long s_final[FINAL_CAP];
    __shared__ int s_hist[256];
    __shared__ int s_scan[256];
    __shared__ int s_red[8];
    __shared__ int s_sel;
    __shared__ int s_nabove, s_ncand, s_nfinal, s_last;

    unsigned* s_sc  = s_pool;             // candidate score bits
    unsigned* s_idx = s_pool + CAND_CAP;  // candidate flat indices

    const int bc   = blockIdx.x;           // 0..2559
    const int b    = bc / CLS;
    const int tid  = threadIdx.x;
    const int lane = tid & 31;
    const int warp = tid >> 5;
    const float* __restrict__ t = hm + (size_t)bc * HW;
    const float T0 = 0.99f;

    if (tid == 0) { s_nabove = 0; s_ncand = 0; s_nfinal = 0; }
    s_hist[tid] = 0;                       // round-1 histogram, filled on append
    __syncthreads();

    // --- Phase 1: dense scan for cells > T0 ---------------------------------
    // Thread strip: cols c0..c0+3, rows r0..r0+15 (warp loads contiguous 128B).
    const int r0 = warp << 4;
    const int c0 = lane << 2;
    {
        const float* rowp = t + (size_t)r0 * WW + c0;
        #pragma unroll 4
        for (int rr = 0; rr < 16; ++rr) {
            if (rr < 12)   // L2 prefetch 4 rows ahead (row r0+rr+4 <= 127)
                asm volatile("prefetch.global.L2 [%0];" :: "l"(rowp + 4 * WW));
            float4 v = *(const float4*)rowp;
            float m = fmaxf(fmaxf(v.x, v.y), fmaxf(v.z, v.w));
            if (m > T0) {                  // rare (~4% of float4 groups)
                int bidx = (r0 + rr) * WW + c0;
                if (v.x > T0) { int p = atomicAdd(&s_nabove, 1); if (p < ABOVE_CAP) s_above[p] = bidx + 0; }
                if (v.y > T0) { int p = atomicAdd(&s_nabove, 1); if (p < ABOVE_CAP) s_above[p] = bidx + 1; }
                if (v.z > T0) { int p = atomicAdd(&s_nabove, 1); if (p < ABOVE_CAP) s_above[p] = bidx + 2; }
                if (v.w > T0) { int p = atomicAdd(&s_nabove, 1); if (p < ABOVE_CAP) s_above[p] = bidx + 3; }
            }
            rowp += WW;
        }
    }
    __syncthreads();
    const int nab = s_nabove;
    const bool overflow = (nab > ABOVE_CAP);

    // --- Phase 2: exact 8-neighbor verify on sparse survivors ---------------
    if (!overflow) {
        int nn = min(nab, ABOVE_CAP);
        for (int i = tid; i < nn; i += 256) {
            int idx = (int)s_above[i];
            int r = idx >> 7, c = idx & (WW - 1);
            const float* p = t + idx;
            float v = *p;
            float mx = v;
            bool okL = (c > 0), okR = (c < WW - 1);
            if (r > 0) {
                mx = fmaxf(mx, p[-WW]);
                if (okL) mx = fmaxf(mx, p[-WW - 1]);
                if (okR) mx = fmaxf(mx, p[-WW + 1]);
            }
            if (okL) mx = fmaxf(mx, p[-1]);
            if (okR) mx = fmaxf(mx, p[1]);
            if (r < HH - 1) {
                mx = fmaxf(mx, p[WW]);
                if (okL) mx = fmaxf(mx, p[WW - 1]);
                if (okR) mx = fmaxf(mx, p[WW + 1]);
            }
            if (mx == v) {                 // exact peak above T0
                unsigned vb = __float_as_uint(v);
                int q = atomicAdd(&s_ncand, 1);
                if (q < CAND_CAP) {
                    s_sc[q]  = vb;
                    s_idx[q] = (unsigned)idx;
                    atomicAdd(&s_hist[vb >> 24], 1);
                }
            }
        }
    }
    __syncthreads();
    int ncand = min(s_ncand, CAND_CAP);

    // --- Fallback: filtered set can't cover top-100 -> full dense NMS -------
    if (overflow || ncand < K) {
        if (tid == 0) s_ncand = 0;
        s_hist[tid] = 0;
        __syncthreads();
        for (int rr = 0; rr < 16; ++rr) {
            int r = r0 + rr;
            for (int j = 0; j < 4; ++j) {
                int c = c0 + j;
                int idx = r * WW + c;
                float v = t[idx];
                float mx = v;
                for (int dr = -1; dr <= 1; ++dr)
                    for (int dc = -1; dc <= 1; ++dc) {
                        int rr2 = r + dr, cc = c + dc;
                        if (rr2 >= 0 && rr2 < HH && cc >= 0 && cc < WW)
                            mx = fmaxf(mx, t[rr2 * WW + cc]);
                    }
                if (mx == v) {
                    unsigned vb = __float_as_uint(v);
                    int q = atomicAdd(&s_ncand, 1);
                    if (q < CAND_CAP) {
                        s_sc[q]  = vb;
                        s_idx[q] = (unsigned)idx;
                        atomicAdd(&s_hist[vb >> 24], 1);
                    }
                }
            }
        }
        __syncthreads();
        ncand = min(s_ncand, CAND_CAP);

        // Still <K peaks (pathological) -> append zero-score suppressed cells
        if (ncand < K) {
            int idx = tid;                 // first 256 cells contain the 100
            int r = idx >> 7, c = idx & (WW - 1);
            float v = t[idx];
            float mval = v;
            for (int dr = -1; dr <= 1; ++dr)
                for (int dc = -1; dc <= 1; ++dc) {
                    int rr2 = r + dr, cc = c + dc;
                    if (rr2 >= 0 && rr2 < HH && cc >= 0 && cc < WW)
                        mval = fmaxf(mval, t[rr2 * WW + cc]);
                }
            if (mval != v) {               // suppressed: value 0 after keep-mask
                int q = atomicAdd(&s_ncand, 1);
                if (q < CAND_CAP) {
                    s_sc[q]  = 0u;
                    s_idx[q] = (unsigned)idx;
                    atomicAdd(&s_hist[0], 1);
                }
            }
            __syncthreads();
            ncand = min(s_ncand, CAND_CAP);
        }
    }

    // --- Radix-select on u32 score: floor Ts, count(>=Ts) in [K, FINAL_CAP] -
    unsigned Ts;
    {
        int need = K;
        int total_above = 0;
        unsigned prefix = 0;
        int shift = 24;                    // round-1 histogram already built
        for (;;) {
            suffix_scan_store(s_hist, s_scan, s_red, tid, lane, warp);
            {
                int d = tid;
                int suf  = s_scan[255 - d];
                int suf1 = (d == 255) ? 0 : s_scan[254 - d];
                if (suf >= need && suf1 < need) s_sel = d;
            }
            __syncthreads();
            int dsel  = s_sel;
            int A     = (dsel == 255) ? 0 : s_scan[254 - dsel];
            int inbin = s_scan[255 - dsel] - A;
            prefix = (prefix << 8) | (unsigned)dsel;
            total_above += A;
            need -= A;
            if (total_above + inbin <= FINAL_CAP || shift == 0) {
                Ts = prefix << shift;
                break;
            }
            shift -= 8;
            __syncthreads();               // protect s_scan/s_sel
            s_hist[tid] = 0;
            __syncthreads();
            for (int i = tid; i < ncand; i += 256) {
                unsigned sb = s_sc[i];
                if ((sb >> (shift + 8)) == prefix)
                    atomicAdd(&s_hist[(sb >> shift) & 255u], 1);
            }
            __syncthreads();
        }
    }
    __syncthreads();

    // --- Collect survivors (<=256) as u64 keys and rank-emit ----------------
    for (int i = tid; i < ncand; i += 256) {
        unsigned sb = s_sc[i];
        if (sb >= Ts) {
            int p = atomicAdd(&s_nfinal, 1);
            if (p < FINAL_CAP)
                s_final[p] = ((unsigned long long)sb << 32) | (unsigned)(~s_idx[i]);
        }
    }
    __syncthreads();
    {
        int nf = min(s_nfinal, FINAL_CAP);
        if (tid < nf) {
            unsigned long long my = s_final[tid];
            int rank = 0;
            #pragma unroll 4
            for (int i = 0; i < nf; ++i) rank += (s_final[i] > my) ? 1 : 0;
            if (rank < K) {
                out[OFF_SC + bc * K + rank] = __uint_as_float((unsigned)(my >> 32));
                g_idx1[bc * K + rank] = (int)(~(unsigned)my);
            }
        }
    }

    // --- Batch completion: last CTA of batch b runs stage2 inline -----------
    __threadfence();
    __syncthreads();
    if (tid == 0) {
        int v = atomicAdd(&g_done[b], 1);
        s_last = (v == CLS - 1) ? 1 : 0;
        if (v == CLS - 1) atomicExch(&g_done[b], 0);   // reset for graph replay
    }
    __syncthreads();
    if (!s_last) return;
    __threadfence();

    // ======================= Inline stage 2 for batch b ======================
    const int NC     = CLS * K;                        // 8000
    const int NCACHE = 2 * CAND_CAP;                   // 6144 u32 cache slots
    const float* __restrict__ sc = out + OFF_SC + (size_t)b * NC;

    s_hist[tid] = 0;
    if (tid == 0) s_nfinal = 0;
    __syncthreads();

    // load + round-1 histogram in one pass
    for (int i = tid; i < NC; i += 256) {
        unsigned sb = __float_as_uint(__ldg(&sc[i]));
        if (i < NCACHE) s_pool[i] = sb;
        atomicAdd(&s_hist[sb >> 24], 1);
    }
    __syncthreads();

    unsigned Ts2;
    {
        int need = K;
        int total_above = 0;
        unsigned prefix = 0;
        int shift = 24;
        for (;;) {
            suffix_scan_store(s_hist, s_scan, s_red, tid, lane, warp);
            {
                int d = tid;
                int suf  = s_scan[255 - d];
                int suf1 = (d == 255) ? 0 : s_scan[254 - d];
                if (suf >= need && suf1 < need) s_sel = d;
            }
            __syncthreads();
            int dsel  = s_sel;
            int A     = (dsel == 255) ? 0 : s_scan[254 - dsel];
            int inbin = s_scan[255 - dsel] - A;
            prefix = (prefix << 8) | (unsigned)dsel;
            total_above += A;
            need -= A;
            if (total_above + inbin <= FINAL_CAP || shift == 0) {
                Ts2 = prefix << shift;
                break;
            }
            shift -= 8;
            __syncthreads();
            s_hist[tid] = 0;
            __syncthreads();
            for (int i = tid; i < NC; i += 256) {
                unsigned sb = (i < NCACHE) ? s_pool[i]
                                           : __float_as_uint(__ldg(&sc[i]));
                if ((sb >> (shift + 8)) == prefix)
                    atomicAdd(&s_hist[(sb >> shift) & 255u], 1);
            }
            __syncthreads();
        }
    }
    __syncthreads();

    for (int i = tid; i < NC; i += 256) {
        unsigned sb = (i < NCACHE) ? s_pool[i] : __float_as_uint(__ldg(&sc[i]));
        if (sb >= Ts2) {
            int p = atomicAdd(&s_nfinal, 1);
            if (p < FINAL_CAP)
                s_final[p] = ((unsigned long long)sb << 32) | (unsigned)(~(unsigned)i);
        }
    }
    __syncthreads();
    {
        int nf = min(s_nfinal, FINAL_CAP);
        if (tid < nf) {
            unsigned long long my = s_final[tid];
            int rank = 0;
            #pragma unroll 4
            for (int i = 0; i < nf; ++i) rank += (s_final[i] > my) ? 1 : 0;
            if (rank < K) {
                int ci     = (int)(~(unsigned)my);           // combined idx [0,8000)
                int classe = ci / K;
                int flat   = g_idx1[b * NC + ci];
                out[OFF_IND  + b * K + rank] = (float)flat;
                out[OFF_CLSO + b * K + rank] = (float)classe;
                out[OFF_YS   + b * K + rank] = (float)(flat >> 7);   // y = flat / 128
                out[OFF_XS   + b * K + rank] = (float)(flat & 127);  // x = flat % 128
            }
        }
    }
}

// ---------------------------------------------------------------------------
extern "C" void kernel_launch(void* const* d_in, const int* in_sizes, int n_in,
                              void* d_out, int out_size)
{
    const float* hm = (const float*)d_in[0];
    float* out = (float*)d_out;
    decode_kernel<<<BS * CLS, 256>>>(hm, out);
}